// round 13
// baseline (speedup 1.0000x reference)
#include <cuda_runtime.h>

#define B 256
#define D 128
#define NEG 1024
#define SAMPLES 300000
#define TEMPR 0.07f
#define EPS 1e-12f

// intra-kernel ordering counters (zero at load; reset at end of every call)
__device__ unsigned int g_done;   // copy blocks completed
__device__ unsigned int g_fin;    // finalize blocks past scatter

__device__ __forceinline__ float warp_sum(float v) {
#pragma unroll
    for (int o = 16; o; o >>= 1) v += __shfl_down_sync(0xffffffffu, v, o);
    return v;
}

__device__ __forceinline__ float warp_sum_xor(float v) {
#pragma unroll
    for (int o = 16; o; o >>= 1) v += __shfl_xor_sync(0xffffffffu, v, o);
    return v;
}

// block-wide sum for 512 threads (16 warps), broadcast
__device__ __forceinline__ float block_sum512(float v, volatile float* sm) {
    int lane = threadIdx.x & 31, w = threadIdx.x >> 5;
    float s = warp_sum(v);
    if (lane == 0) sm[w] = s;
    __syncthreads();
    float r = 0.f;
    if (threadIdx.x == 0) {
#pragma unroll
        for (int i = 0; i < 16; i++) r += sm[i];
        sm[16] = r;
    }
    __syncthreads();
    r = sm[16];
    __syncthreads();
    return r;
}

// int64 vs int32 detection (JAX x64 demotion hedge)
__device__ __forceinline__ bool is_i64(const void* p) {
    const int* q = (const int*)p;
    return ((q[1] | q[3] | q[5] | q[7]) == 0);
}
__device__ __forceinline__ long long ld_idx(const void* p, long long i, bool is64) {
    return is64 ? ((const long long*)p)[i] : (long long)((const int*)p)[i];
}

__device__ __forceinline__ float dot4(float4 a, float4 b) {
    return a.x * b.x + a.y * b.y + a.z * b.z + a.w * b.w;
}

// ---------------------------------------------------------------------------
// Single fused kernel, grid 2064 x 512:
//   bx <  2048, odd  -> score block (1024 blocks, 256 negs each)
//   bx <  2048, even -> copy block  (1024 blocks, streaming copy; signals
//                       completion via g_done)
//   bx >= 2048       -> finalize block (16 x 16 warps = warp-per-row):
//                       pos scores immediately; momentum rows kept in
//                       REGISTERS; spin until all copy blocks signal, then
//                       scatter (last-occurrence-wins dedup). Counters are
//                       reset by the unique last finalize block -> replays
//                       are deterministic.
// ---------------------------------------------------------------------------
__global__ __launch_bounds__(512) void fused_kernel(
    const float* __restrict__ audio_emb, const float* __restrict__ video_emb,
    const float* __restrict__ amem, const float* __restrict__ vmem,
    const void* __restrict__ indices, const void* __restrict__ negs,
    float* __restrict__ out_scores,
    float* __restrict__ out_amem, float* __restrict__ out_vmem) {

    const int bx = blockIdx.x;
    const int t = threadIdx.x;

    if (bx >= 2048) {
        // ----------------------- finalize block ------------------------
        const int lane = t & 31;
        const int b = (bx - 2048) * 16 + (t >> 5);
        const bool is64 = is_i64(indices);

        const float4 a4 = *(const float4*)(audio_emb + b * D + lane * 4);
        const float4 v4 = *(const float4*)(video_emb + b * D + lane * 4);
        float da = fmaxf(sqrtf(warp_sum_xor(dot4(a4, a4))), EPS);
        float dv = fmaxf(sqrtf(warp_sum_xor(dot4(v4, v4))), EPS);
        float4 na4 = make_float4(a4.x / da, a4.y / da, a4.z / da, a4.w / da);
        float4 nv4 = make_float4(v4.x / dv, v4.y / dv, v4.z / dv, v4.w / dv);

        const long long idx = ld_idx(indices, b, is64);
        const float4 pa4 = *(const float4*)(amem + idx * D + lane * 4);
        const float4 pv4 = *(const float4*)(vmem + idx * D + lane * 4);

        float d_apv = warp_sum_xor(dot4(na4, pv4));
        float d_vpa = warp_sum_xor(dot4(nv4, pa4));
        float d_apa = warp_sum_xor(dot4(na4, pa4));
        float d_vpv = warp_sum_xor(dot4(nv4, pv4));
        if (lane == 0) {
            const long long S = (long long)B * (1 + NEG);
            out_scores[0 * S + (long long)b * (1 + NEG)] = d_apv / TEMPR;
            out_scores[1 * S + (long long)b * (1 + NEG)] = d_vpa / TEMPR;
            out_scores[2 * S + (long long)b * (1 + NEG)] = d_apa / TEMPR;
            out_scores[3 * S + (long long)b * (1 + NEG)] = d_vpv / TEMPR;
        }

        // last-occurrence-wins duplicate scan, lane-parallel
        bool dup = false;
        for (int bb = b + 1 + lane; bb < B; bb += 32)
            dup |= (ld_idx(indices, bb, is64) == idx);
        dup = __any_sync(0xffffffffu, dup);

        // momentum rows, kept in registers across the spin
        float4 ma4 = make_float4(pa4.x * 0.5f + na4.x * 0.5f, pa4.y * 0.5f + na4.y * 0.5f,
                                 pa4.z * 0.5f + na4.z * 0.5f, pa4.w * 0.5f + na4.w * 0.5f);
        float4 mv4 = make_float4(pv4.x * 0.5f + nv4.x * 0.5f, pv4.y * 0.5f + nv4.y * 0.5f,
                                 pv4.z * 0.5f + nv4.z * 0.5f, pv4.w * 0.5f + nv4.w * 0.5f);
        float dma = fmaxf(sqrtf(warp_sum_xor(dot4(ma4, ma4))), EPS);
        float dmv = fmaxf(sqrtf(warp_sum_xor(dot4(mv4, mv4))), EPS);
        float4 ua4 = make_float4(ma4.x / dma, ma4.y / dma, ma4.z / dma, ma4.w / dma);
        float4 uv4 = make_float4(mv4.x / dmv, mv4.y / dmv, mv4.z / dmv, mv4.w / dmv);

        // wait for all 1024 copy blocks (release via their threadfence+atomic)
        if (t == 0) {
            volatile unsigned int* dp = &g_done;
            while (*dp < 1024u) __nanosleep(128);
        }
        __syncthreads();
        __threadfence();   // acquire: copy's stores now visible/ordered

        if (!dup) {
            *(float4*)(out_amem + idx * D + lane * 4) = ua4;
            *(float4*)(out_vmem + idx * D + lane * 4) = uv4;
        }

        // deterministic counter reset: unique last finalize block does it
        __syncthreads();
        if (t == 0) {
            __threadfence();
            unsigned int r = atomicAdd(&g_fin, 1u);
            if (r == 15u) { g_done = 0u; g_fin = 0u; __threadfence(); }
        }
    } else if (bx & 1) {
        // ------------------------- score block -------------------------
        const int sid = bx >> 1;            // 0..1023
        const int b = sid >> 2;
        const int n0 = (sid & 3) * 256;
        const int lane = t & 31;
        const int w = t >> 5;

        __shared__ float red[17];
        __shared__ __align__(16) float na_s[D];
        __shared__ __align__(16) float nv_s[D];
        __shared__ float sbuf[4][256];

        float a = 0.f, v = 0.f;
        if (t < D) { a = audio_emb[b * D + t]; v = video_emb[b * D + t]; }
        float sa = block_sum512(a * a, red);
        float sv = block_sum512(v * v, red);
        if (t < D) {
            na_s[t] = a / fmaxf(sqrtf(sa), EPS);
            nv_s[t] = v / fmaxf(sqrtf(sv), EPS);
        }
        __syncthreads();

        const bool is64i = is_i64(indices);
        const bool is64n = is_i64(negs);
        const long long idx = ld_idx(indices, b, is64i);

        const float4 na4 = *(const float4*)(na_s + lane * 4);
        const float4 nv4 = *(const float4*)(nv_s + lane * 4);

#pragma unroll 2
        for (int i = w; i < 256; i += 16) {
            long long neg = ld_idx(negs, (long long)b * NEG + n0 + i, is64n);
            long long row = neg + (neg >= idx ? 1 : 0);
            const float4 av = *(const float4*)(amem + row * D + lane * 4);
            const float4 vv = *(const float4*)(vmem + row * D + lane * 4);

            float s_aa = av.x * na4.x + av.y * na4.y + av.z * na4.z + av.w * na4.w;
            float s_av = av.x * nv4.x + av.y * nv4.y + av.z * nv4.z + av.w * nv4.w;
            float s_va = vv.x * na4.x + vv.y * na4.y + vv.z * na4.z + vv.w * na4.w;
            float s_vv = vv.x * nv4.x + vv.y * nv4.y + vv.z * nv4.z + vv.w * nv4.w;

#pragma unroll
            for (int o = 16; o; o >>= 1) {
                s_aa += __shfl_down_sync(0xffffffffu, s_aa, o);
                s_av += __shfl_down_sync(0xffffffffu, s_av, o);
                s_va += __shfl_down_sync(0xffffffffu, s_va, o);
                s_vv += __shfl_down_sync(0xffffffffu, s_vv, o);
            }
            if (lane == 0) {
                // [0]=neg_v·na  [1]=neg_a·nv  [2]=neg_a·na  [3]=neg_v·nv
                sbuf[0][i] = s_va;
                sbuf[1][i] = s_av;
                sbuf[2][i] = s_aa;
                sbuf[3][i] = s_vv;
            }
        }
        __syncthreads();

        const long long S = (long long)B * (1 + NEG);
        float* dst = out_scores + (long long)b * (1 + NEG) + 1 + n0;
        if (t < 256) {
#pragma unroll
            for (int k = 0; k < 4; k++)
                dst[k * S + t] = sbuf[k][t] / TEMPR;
        }
    } else {
        // ------------------------- copy block --------------------------
        const int cid = bx >> 1;            // 0..1023
        const size_t N4 = (size_t)SAMPLES * D / 4;
        const size_t stride = (size_t)1024 * 512;
        const float4* as = (const float4*)amem;
        const float4* vs = (const float4*)vmem;
        float4* ad = (float4*)out_amem;
        float4* vd = (float4*)out_vmem;

        size_t i = (size_t)cid * 512 + t;
        for (; i + 3 * stride < N4; i += 4 * stride) {
            float4 x0 = __ldcs(as + i);
            float4 x1 = __ldcs(as + i + stride);
            float4 x2 = __ldcs(as + i + 2 * stride);
            float4 x3 = __ldcs(as + i + 3 * stride);
            __stcs(ad + i, x0);
            __stcs(ad + i + stride, x1);
            __stcs(ad + i + 2 * stride, x2);
            __stcs(ad + i + 3 * stride, x3);
            float4 y0 = __ldcs(vs + i);
            float4 y1 = __ldcs(vs + i + stride);
            float4 y2 = __ldcs(vs + i + 2 * stride);
            float4 y3 = __ldcs(vs + i + 3 * stride);
            __stcs(vd + i, y0);
            __stcs(vd + i + stride, y1);
            __stcs(vd + i + 2 * stride, y2);
            __stcs(vd + i + 3 * stride, y3);
        }
        for (; i < N4; i += stride) {
            __stcs(ad + i, __ldcs(as + i));
            __stcs(vd + i, __ldcs(vs + i));
        }

        // release: make this block's copies visible, then signal completion
        __syncthreads();
        if (t == 0) {
            __threadfence();
            atomicAdd(&g_done, 1u);
        }
    }
}

extern "C" void kernel_launch(void* const* d_in, const int* in_sizes, int n_in,
                              void* d_out, int out_size) {
    const float* audio_emb = (const float*)d_in[0];
    const float* video_emb = (const float*)d_in[1];
    const float* amem = (const float*)d_in[2];
    const float* vmem = (const float*)d_in[3];
    const void* indices = d_in[4];
    const void* negs = d_in[5];

    float* out = (float*)d_out;
    float* out_scores = out;                                 // [4,256,1025]
    float* out_amem = out + (size_t)4 * B * (1 + NEG);       // [300000,128]
    float* out_vmem = out_amem + (size_t)SAMPLES * D;        // [300000,128]

    fused_kernel<<<2064, 512>>>(audio_emb, video_emb, amem, vmem, indices,
                                negs, out_scores, out_amem, out_vmem);
}

// round 14
// speedup vs baseline: 1.0868x; 1.0868x over previous
#include <cuda_runtime.h>

#define B 256
#define D 128
#define NEG 1024
#define SAMPLES 300000
#define TEMPR 0.07f
#define EPS 1e-12f

// scratch + ordering counters (allocation-free rule; reset each call)
__device__ __align__(16) float g_upd_a[B * D];
__device__ __align__(16) float g_upd_v[B * D];
__device__ int g_dup[B];
__device__ unsigned int g_done;   // copy blocks completed
__device__ unsigned int g_fin;    // finalize blocks past scatter

__device__ __forceinline__ float warp_sum(float v) {
#pragma unroll
    for (int o = 16; o; o >>= 1) v += __shfl_down_sync(0xffffffffu, v, o);
    return v;
}

__device__ __forceinline__ float warp_sum_xor(float v) {
#pragma unroll
    for (int o = 16; o; o >>= 1) v += __shfl_xor_sync(0xffffffffu, v, o);
    return v;
}

// block-wide sum for 512 threads (16 warps), broadcast
__device__ __forceinline__ float block_sum512(float v, volatile float* sm) {
    int lane = threadIdx.x & 31, w = threadIdx.x >> 5;
    float s = warp_sum(v);
    if (lane == 0) sm[w] = s;
    __syncthreads();
    float r = 0.f;
    if (threadIdx.x == 0) {
#pragma unroll
        for (int i = 0; i < 16; i++) r += sm[i];
        sm[16] = r;
    }
    __syncthreads();
    r = sm[16];
    __syncthreads();
    return r;
}

// int64 vs int32 detection (JAX x64 demotion hedge)
__device__ __forceinline__ bool is_i64(const void* p) {
    const int* q = (const int*)p;
    return ((q[1] | q[3] | q[5] | q[7]) == 0);
}
__device__ __forceinline__ long long ld_idx(const void* p, long long i, bool is64) {
    return is64 ? ((const long long*)p)[i] : (long long)((const int*)p)[i];
}

__device__ __forceinline__ float dot4(float4 a, float4 b) {
    return a.x * b.x + a.y * b.y + a.z * b.z + a.w * b.w;
}

// ---------------------------------------------------------------------------
// Single fused kernel, grid 2064 x 512, __launch_bounds__(512,3):
// the 42-reg cap keeps 3 blocks/SM resident (the 43+ reg configs measured
// ~14us slower — occupancy cliff). Spills, if any, land in the cold
// finalize branch (16 of 2064 blocks).
//   bx <  2048, odd  -> score block (1024 blocks, 256 negs each)
//   bx <  2048, even -> copy block  (1024 blocks; release-signals g_done)
//   bx >= 2048       -> finalize block (warp-per-row x16): pos scores, then
//                       updated rows -> scratch, spin for copy completion,
//                       scatter from scratch (last-occurrence-wins dedup).
// ---------------------------------------------------------------------------
__global__ void __launch_bounds__(512, 3) fused_kernel(
    const float* __restrict__ audio_emb, const float* __restrict__ video_emb,
    const float* __restrict__ amem, const float* __restrict__ vmem,
    const void* __restrict__ indices, const void* __restrict__ negs,
    float* __restrict__ out_scores,
    float* __restrict__ out_amem, float* __restrict__ out_vmem) {

    const int bx = blockIdx.x;
    const int t = threadIdx.x;

    if (bx >= 2048) {
        // ----------------------- finalize block ------------------------
        const int lane = t & 31;
        const int b = (bx - 2048) * 16 + (t >> 5);
        const bool is64 = is_i64(indices);

        const float4 a4 = *(const float4*)(audio_emb + b * D + lane * 4);
        const float4 v4 = *(const float4*)(video_emb + b * D + lane * 4);
        float da = fmaxf(sqrtf(warp_sum_xor(dot4(a4, a4))), EPS);
        float dv = fmaxf(sqrtf(warp_sum_xor(dot4(v4, v4))), EPS);
        float4 na4 = make_float4(a4.x / da, a4.y / da, a4.z / da, a4.w / da);
        float4 nv4 = make_float4(v4.x / dv, v4.y / dv, v4.z / dv, v4.w / dv);

        const long long idx = ld_idx(indices, b, is64);
        const float4 pa4 = *(const float4*)(amem + idx * D + lane * 4);
        const float4 pv4 = *(const float4*)(vmem + idx * D + lane * 4);

        float d_apv = warp_sum_xor(dot4(na4, pv4));
        float d_vpa = warp_sum_xor(dot4(nv4, pa4));
        float d_apa = warp_sum_xor(dot4(na4, pa4));
        float d_vpv = warp_sum_xor(dot4(nv4, pv4));
        if (lane == 0) {
            const long long S = (long long)B * (1 + NEG);
            out_scores[0 * S + (long long)b * (1 + NEG)] = d_apv / TEMPR;
            out_scores[1 * S + (long long)b * (1 + NEG)] = d_vpa / TEMPR;
            out_scores[2 * S + (long long)b * (1 + NEG)] = d_apa / TEMPR;
            out_scores[3 * S + (long long)b * (1 + NEG)] = d_vpv / TEMPR;
        }

        // last-occurrence-wins duplicate scan, lane-parallel
        bool dup = false;
        for (int bb = b + 1 + lane; bb < B; bb += 32)
            dup |= (ld_idx(indices, bb, is64) == idx);
        dup = __any_sync(0xffffffffu, dup);
        if (lane == 0) g_dup[b] = dup ? 1 : 0;

        // momentum rows -> scratch (NOTHING held in regs across the spin)
        float4 ma4 = make_float4(pa4.x * 0.5f + na4.x * 0.5f, pa4.y * 0.5f + na4.y * 0.5f,
                                 pa4.z * 0.5f + na4.z * 0.5f, pa4.w * 0.5f + na4.w * 0.5f);
        float4 mv4 = make_float4(pv4.x * 0.5f + nv4.x * 0.5f, pv4.y * 0.5f + nv4.y * 0.5f,
                                 pv4.z * 0.5f + nv4.z * 0.5f, pv4.w * 0.5f + nv4.w * 0.5f);
        float dma = fmaxf(sqrtf(warp_sum_xor(dot4(ma4, ma4))), EPS);
        float dmv = fmaxf(sqrtf(warp_sum_xor(dot4(mv4, mv4))), EPS);
        *(float4*)(g_upd_a + b * D + lane * 4) =
            make_float4(ma4.x / dma, ma4.y / dma, ma4.z / dma, ma4.w / dma);
        *(float4*)(g_upd_v + b * D + lane * 4) =
            make_float4(mv4.x / dmv, mv4.y / dmv, mv4.z / dmv, mv4.w / dmv);

        // wait for all 1024 copy blocks (their threadfence+atomic = release)
        if (t == 0) {
            volatile unsigned int* dp = &g_done;
            while (*dp < 1024u) __nanosleep(128);
        }
        __syncthreads();
        __threadfence();   // acquire

        if (!g_dup[b]) {
            *(float4*)(out_amem + idx * D + lane * 4) =
                *(const float4*)(g_upd_a + b * D + lane * 4);
            *(float4*)(out_vmem + idx * D + lane * 4) =
                *(const float4*)(g_upd_v + b * D + lane * 4);
        }

        // deterministic counter reset by the unique last finalize block
        __syncthreads();
        if (t == 0) {
            __threadfence();
            unsigned int r = atomicAdd(&g_fin, 1u);
            if (r == 15u) { g_done = 0u; g_fin = 0u; __threadfence(); }
        }
    } else if (bx & 1) {
        // ------------------------- score block -------------------------
        const int sid = bx >> 1;            // 0..1023
        const int b = sid >> 2;
        const int n0 = (sid & 3) * 256;
        const int lane = t & 31;
        const int w = t >> 5;

        __shared__ float red[17];
        __shared__ __align__(16) float na_s[D];
        __shared__ __align__(16) float nv_s[D];
        __shared__ float sbuf[4][256];

        float a = 0.f, v = 0.f;
        if (t < D) { a = audio_emb[b * D + t]; v = video_emb[b * D + t]; }
        float sa = block_sum512(a * a, red);
        float sv = block_sum512(v * v, red);
        if (t < D) {
            na_s[t] = a / fmaxf(sqrtf(sa), EPS);
            nv_s[t] = v / fmaxf(sqrtf(sv), EPS);
        }
        __syncthreads();

        const bool is64i = is_i64(indices);
        const bool is64n = is_i64(negs);
        const long long idx = ld_idx(indices, b, is64i);

        const float4 na4 = *(const float4*)(na_s + lane * 4);
        const float4 nv4 = *(const float4*)(nv_s + lane * 4);

#pragma unroll 2
        for (int i = w; i < 256; i += 16) {
            long long neg = ld_idx(negs, (long long)b * NEG + n0 + i, is64n);
            long long row = neg + (neg >= idx ? 1 : 0);
            const float4 av = *(const float4*)(amem + row * D + lane * 4);
            const float4 vv = *(const float4*)(vmem + row * D + lane * 4);

            float s_aa = av.x * na4.x + av.y * na4.y + av.z * na4.z + av.w * na4.w;
            float s_av = av.x * nv4.x + av.y * nv4.y + av.z * nv4.z + av.w * nv4.w;
            float s_va = vv.x * na4.x + vv.y * na4.y + vv.z * na4.z + vv.w * na4.w;
            float s_vv = vv.x * nv4.x + vv.y * nv4.y + vv.z * nv4.z + vv.w * nv4.w;

#pragma unroll
            for (int o = 16; o; o >>= 1) {
                s_aa += __shfl_down_sync(0xffffffffu, s_aa, o);
                s_av += __shfl_down_sync(0xffffffffu, s_av, o);
                s_va += __shfl_down_sync(0xffffffffu, s_va, o);
                s_vv += __shfl_down_sync(0xffffffffu, s_vv, o);
            }
            if (lane == 0) {
                // [0]=neg_v·na  [1]=neg_a·nv  [2]=neg_a·na  [3]=neg_v·nv
                sbuf[0][i] = s_va;
                sbuf[1][i] = s_av;
                sbuf[2][i] = s_aa;
                sbuf[3][i] = s_vv;
            }
        }
        __syncthreads();

        const long long S = (long long)B * (1 + NEG);
        float* dst = out_scores + (long long)b * (1 + NEG) + 1 + n0;
        if (t < 256) {
#pragma unroll
            for (int k = 0; k < 4; k++)
                dst[k * S + t] = sbuf[k][t] / TEMPR;
        }
    } else {
        // ------------------------- copy block --------------------------
        const int cid = bx >> 1;            // 0..1023
        const size_t N4 = (size_t)SAMPLES * D / 4;
        const size_t stride = (size_t)1024 * 512;
        const float4* as = (const float4*)amem;
        const float4* vs = (const float4*)vmem;
        float4* ad = (float4*)out_amem;
        float4* vd = (float4*)out_vmem;

        size_t i = (size_t)cid * 512 + t;
        for (; i + 3 * stride < N4; i += 4 * stride) {
            float4 x0 = __ldcs(as + i);
            float4 x1 = __ldcs(as + i + stride);
            float4 x2 = __ldcs(as + i + 2 * stride);
            float4 x3 = __ldcs(as + i + 3 * stride);
            __stcs(ad + i, x0);
            __stcs(ad + i + stride, x1);
            __stcs(ad + i + 2 * stride, x2);
            __stcs(ad + i + 3 * stride, x3);
            float4 y0 = __ldcs(vs + i);
            float4 y1 = __ldcs(vs + i + stride);
            float4 y2 = __ldcs(vs + i + 2 * stride);
            float4 y3 = __ldcs(vs + i + 3 * stride);
            __stcs(vd + i, y0);
            __stcs(vd + i + stride, y1);
            __stcs(vd + i + 2 * stride, y2);
            __stcs(vd + i + 3 * stride, y3);
        }
        for (; i < N4; i += stride) {
            __stcs(ad + i, __ldcs(as + i));
            __stcs(vd + i, __ldcs(vs + i));
        }

        // release: make this block's copies visible, then signal completion
        __syncthreads();
        if (t == 0) {
            __threadfence();
            atomicAdd(&g_done, 1u);
        }
    }
}

extern "C" void kernel_launch(void* const* d_in, const int* in_sizes, int n_in,
                              void* d_out, int out_size) {
    const float* audio_emb = (const float*)d_in[0];
    const float* video_emb = (const float*)d_in[1];
    const float* amem = (const float*)d_in[2];
    const float* vmem = (const float*)d_in[3];
    const void* indices = d_in[4];
    const void* negs = d_in[5];

    float* out = (float*)d_out;
    float* out_scores = out;                                 // [4,256,1025]
    float* out_amem = out + (size_t)4 * B * (1 + NEG);       // [300000,128]
    float* out_vmem = out_amem + (size_t)SAMPLES * D;        // [300000,128]

    fused_kernel<<<2064, 512>>>(audio_emb, video_emb, amem, vmem, indices,
                                negs, out_scores, out_amem, out_vmem);
}

// round 15
// speedup vs baseline: 1.1148x; 1.0258x over previous
#include <cuda_runtime.h>

#define B 256
#define D 128
#define NEG 1024
#define SAMPLES 300000
#define TEMPR 0.07f
#define EPS 1e-12f

// scratch + ordering counters (allocation-free rule; reset each call)
__device__ __align__(16) float g_upd_a[B * D];
__device__ __align__(16) float g_upd_v[B * D];
__device__ int g_dup[B];
__device__ unsigned int g_done;   // copy blocks completed
__device__ unsigned int g_fin;    // finalize blocks past scatter

__device__ __forceinline__ float warp_sum(float v) {
#pragma unroll
    for (int o = 16; o; o >>= 1) v += __shfl_down_sync(0xffffffffu, v, o);
    return v;
}

__device__ __forceinline__ float warp_sum_xor(float v) {
#pragma unroll
    for (int o = 16; o; o >>= 1) v += __shfl_xor_sync(0xffffffffu, v, o);
    return v;
}

// block-wide sum for 512 threads (16 warps), broadcast
__device__ __forceinline__ float block_sum512(float v, volatile float* sm) {
    int lane = threadIdx.x & 31, w = threadIdx.x >> 5;
    float s = warp_sum(v);
    if (lane == 0) sm[w] = s;
    __syncthreads();
    float r = 0.f;
    if (threadIdx.x == 0) {
#pragma unroll
        for (int i = 0; i < 16; i++) r += sm[i];
        sm[16] = r;
    }
    __syncthreads();
    r = sm[16];
    __syncthreads();
    return r;
}

// int64 vs int32 detection (JAX x64 demotion hedge)
__device__ __forceinline__ bool is_i64(const void* p) {
    const int* q = (const int*)p;
    return ((q[1] | q[3] | q[5] | q[7]) == 0);
}
__device__ __forceinline__ long long ld_idx(const void* p, long long i, bool is64) {
    return is64 ? ((const long long*)p)[i] : (long long)((const int*)p)[i];
}

__device__ __forceinline__ float dot4(float4 a, float4 b) {
    return a.x * b.x + a.y * b.y + a.z * b.z + a.w * b.w;
}

// ---------------------------------------------------------------------------
// Single fused kernel, grid 2064 x 512, __launch_bounds__(512,3) (42-reg cap
// keeps 3 blocks/SM; the 43+ reg configs measured ~14us slower).
//   bx <  2048, odd  -> score block (1024 blocks, 256 negs each)
//   bx <  2048, even -> copy block  (1024 blocks; release-signals g_done).
//                       Copy READS are now default-cached (not __ldcs):
//                       every gathered row is also read once by the copy, so
//                       keeping streamed lines in L2 lets gathers hit them.
//                       Stores remain __stcs (output has no reader).
//   bx >= 2048       -> finalize block (warp-per-row x16): pos scores, then
//                       updated rows -> scratch, spin for copy completion,
//                       scatter from scratch (last-occurrence-wins dedup).
// ---------------------------------------------------------------------------
__global__ void __launch_bounds__(512, 3) fused_kernel(
    const float* __restrict__ audio_emb, const float* __restrict__ video_emb,
    const float* __restrict__ amem, const float* __restrict__ vmem,
    const void* __restrict__ indices, const void* __restrict__ negs,
    float* __restrict__ out_scores,
    float* __restrict__ out_amem, float* __restrict__ out_vmem) {

    const int bx = blockIdx.x;
    const int t = threadIdx.x;

    if (bx >= 2048) {
        // ----------------------- finalize block ------------------------
        const int lane = t & 31;
        const int b = (bx - 2048) * 16 + (t >> 5);
        const bool is64 = is_i64(indices);

        const float4 a4 = *(const float4*)(audio_emb + b * D + lane * 4);
        const float4 v4 = *(const float4*)(video_emb + b * D + lane * 4);
        float da = fmaxf(sqrtf(warp_sum_xor(dot4(a4, a4))), EPS);
        float dv = fmaxf(sqrtf(warp_sum_xor(dot4(v4, v4))), EPS);
        float4 na4 = make_float4(a4.x / da, a4.y / da, a4.z / da, a4.w / da);
        float4 nv4 = make_float4(v4.x / dv, v4.y / dv, v4.z / dv, v4.w / dv);

        const long long idx = ld_idx(indices, b, is64);
        const float4 pa4 = *(const float4*)(amem + idx * D + lane * 4);
        const float4 pv4 = *(const float4*)(vmem + idx * D + lane * 4);

        float d_apv = warp_sum_xor(dot4(na4, pv4));
        float d_vpa = warp_sum_xor(dot4(nv4, pa4));
        float d_apa = warp_sum_xor(dot4(na4, pa4));
        float d_vpv = warp_sum_xor(dot4(nv4, pv4));
        if (lane == 0) {
            const long long S = (long long)B * (1 + NEG);
            out_scores[0 * S + (long long)b * (1 + NEG)] = d_apv / TEMPR;
            out_scores[1 * S + (long long)b * (1 + NEG)] = d_vpa / TEMPR;
            out_scores[2 * S + (long long)b * (1 + NEG)] = d_apa / TEMPR;
            out_scores[3 * S + (long long)b * (1 + NEG)] = d_vpv / TEMPR;
        }

        // last-occurrence-wins duplicate scan, lane-parallel
        bool dup = false;
        for (int bb = b + 1 + lane; bb < B; bb += 32)
            dup |= (ld_idx(indices, bb, is64) == idx);
        dup = __any_sync(0xffffffffu, dup);
        if (lane == 0) g_dup[b] = dup ? 1 : 0;

        // momentum rows -> scratch (NOTHING held in regs across the spin)
        float4 ma4 = make_float4(pa4.x * 0.5f + na4.x * 0.5f, pa4.y * 0.5f + na4.y * 0.5f,
                                 pa4.z * 0.5f + na4.z * 0.5f, pa4.w * 0.5f + na4.w * 0.5f);
        float4 mv4 = make_float4(pv4.x * 0.5f + nv4.x * 0.5f, pv4.y * 0.5f + nv4.y * 0.5f,
                                 pv4.z * 0.5f + nv4.z * 0.5f, pv4.w * 0.5f + nv4.w * 0.5f);
        float dma = fmaxf(sqrtf(warp_sum_xor(dot4(ma4, ma4))), EPS);
        float dmv = fmaxf(sqrtf(warp_sum_xor(dot4(mv4, mv4))), EPS);
        *(float4*)(g_upd_a + b * D + lane * 4) =
            make_float4(ma4.x / dma, ma4.y / dma, ma4.z / dma, ma4.w / dma);
        *(float4*)(g_upd_v + b * D + lane * 4) =
            make_float4(mv4.x / dmv, mv4.y / dmv, mv4.z / dmv, mv4.w / dmv);

        // wait for all 1024 copy blocks (their threadfence+atomic = release)
        if (t == 0) {
            volatile unsigned int* dp = &g_done;
            while (*dp < 1024u) __nanosleep(128);
        }
        __syncthreads();
        __threadfence();   // acquire

        if (!g_dup[b]) {
            *(float4*)(out_amem + idx * D + lane * 4) =
                *(const float4*)(g_upd_a + b * D + lane * 4);
            *(float4*)(out_vmem + idx * D + lane * 4) =
                *(const float4*)(g_upd_v + b * D + lane * 4);
        }

        // deterministic counter reset by the unique last finalize block
        __syncthreads();
        if (t == 0) {
            __threadfence();
            unsigned int r = atomicAdd(&g_fin, 1u);
            if (r == 15u) { g_done = 0u; g_fin = 0u; __threadfence(); }
        }
    } else if (bx & 1) {
        // ------------------------- score block -------------------------
        const int sid = bx >> 1;            // 0..1023
        const int b = sid >> 2;
        const int n0 = (sid & 3) * 256;
        const int lane = t & 31;
        const int w = t >> 5;

        __shared__ float red[17];
        __shared__ __align__(16) float na_s[D];
        __shared__ __align__(16) float nv_s[D];
        __shared__ float sbuf[4][256];

        float a = 0.f, v = 0.f;
        if (t < D) { a = audio_emb[b * D + t]; v = video_emb[b * D + t]; }
        float sa = block_sum512(a * a, red);
        float sv = block_sum512(v * v, red);
        if (t < D) {
            na_s[t] = a / fmaxf(sqrtf(sa), EPS);
            nv_s[t] = v / fmaxf(sqrtf(sv), EPS);
        }
        __syncthreads();

        const bool is64i = is_i64(indices);
        const bool is64n = is_i64(negs);
        const long long idx = ld_idx(indices, b, is64i);

        const float4 na4 = *(const float4*)(na_s + lane * 4);
        const float4 nv4 = *(const float4*)(nv_s + lane * 4);

#pragma unroll 2
        for (int i = w; i < 256; i += 16) {
            long long neg = ld_idx(negs, (long long)b * NEG + n0 + i, is64n);
            long long row = neg + (neg >= idx ? 1 : 0);
            const float4 av = *(const float4*)(amem + row * D + lane * 4);
            const float4 vv = *(const float4*)(vmem + row * D + lane * 4);

            float s_aa = av.x * na4.x + av.y * na4.y + av.z * na4.z + av.w * na4.w;
            float s_av = av.x * nv4.x + av.y * nv4.y + av.z * nv4.z + av.w * nv4.w;
            float s_va = vv.x * na4.x + vv.y * na4.y + vv.z * na4.z + vv.w * na4.w;
            float s_vv = vv.x * nv4.x + vv.y * nv4.y + vv.z * nv4.z + vv.w * nv4.w;

#pragma unroll
            for (int o = 16; o; o >>= 1) {
                s_aa += __shfl_down_sync(0xffffffffu, s_aa, o);
                s_av += __shfl_down_sync(0xffffffffu, s_av, o);
                s_va += __shfl_down_sync(0xffffffffu, s_va, o);
                s_vv += __shfl_down_sync(0xffffffffu, s_vv, o);
            }
            if (lane == 0) {
                // [0]=neg_v·na  [1]=neg_a·nv  [2]=neg_a·na  [3]=neg_v·nv
                sbuf[0][i] = s_va;
                sbuf[1][i] = s_av;
                sbuf[2][i] = s_aa;
                sbuf[3][i] = s_vv;
            }
        }
        __syncthreads();

        const long long S = (long long)B * (1 + NEG);
        float* dst = out_scores + (long long)b * (1 + NEG) + 1 + n0;
        if (t < 256) {
#pragma unroll
            for (int k = 0; k < 4; k++)
                dst[k * S + t] = sbuf[k][t] / TEMPR;
        }
    } else {
        // ------------------------- copy block --------------------------
        const int cid = bx >> 1;            // 0..1023
        const size_t N4 = (size_t)SAMPLES * D / 4;
        const size_t stride = (size_t)1024 * 512;
        const float4* as = (const float4*)amem;
        const float4* vs = (const float4*)vmem;
        float4* ad = (float4*)out_amem;
        float4* vd = (float4*)out_vmem;

        size_t i = (size_t)cid * 512 + t;
        for (; i + 3 * stride < N4; i += 4 * stride) {
            // default-cached reads: leave streamed rows in L2 for the gathers
            float4 x0 = as[i];
            float4 x1 = as[i + stride];
            float4 x2 = as[i + 2 * stride];
            float4 x3 = as[i + 3 * stride];
            __stcs(ad + i, x0);
            __stcs(ad + i + stride, x1);
            __stcs(ad + i + 2 * stride, x2);
            __stcs(ad + i + 3 * stride, x3);
            float4 y0 = vs[i];
            float4 y1 = vs[i + stride];
            float4 y2 = vs[i + 2 * stride];
            float4 y3 = vs[i + 3 * stride];
            __stcs(vd + i, y0);
            __stcs(vd + i + stride, y1);
            __stcs(vd + i + 2 * stride, y2);
            __stcs(vd + i + 3 * stride, y3);
        }
        for (; i < N4; i += stride) {
            __stcs(ad + i, as[i]);
            __stcs(vd + i, vs[i]);
        }

        // release: make this block's copies visible, then signal completion
        __syncthreads();
        if (t == 0) {
            __threadfence();
            atomicAdd(&g_done, 1u);
        }
    }
}

extern "C" void kernel_launch(void* const* d_in, const int* in_sizes, int n_in,
                              void* d_out, int out_size) {
    const float* audio_emb = (const float*)d_in[0];
    const float* video_emb = (const float*)d_in[1];
    const float* amem = (const float*)d_in[2];
    const float* vmem = (const float*)d_in[3];
    const void* indices = d_in[4];
    const void* negs = d_in[5];

    float* out = (float*)d_out;
    float* out_scores = out;                                 // [4,256,1025]
    float* out_amem = out + (size_t)4 * B * (1 + NEG);       // [300000,128]
    float* out_vmem = out_amem + (size_t)SAMPLES * D;        // [300000,128]

    fused_kernel<<<2064, 512>>>(audio_emb, video_emb, amem, vmem, indices,
                                negs, out_scores, out_amem, out_vmem);
}